// round 5
// baseline (speedup 1.0000x reference)
#include <cuda_runtime.h>
#include <cuda_bf16.h>
#include <cstdint>

// Problem constants (fixed by the dataset)
#define MAX_NODES 100000
#define D_FEAT    128

// Per-node precomputed partial logits.
// A[n] = (emb[n] . W[0, 0:128] + b0 , emb[n] . W[1, 0:128] + b1)   -- source-side
// B[n] = (emb[n] . W[0,128:256]     , emb[n] . W[1,128:256])       -- dest-side
__device__ float2 g_A[MAX_NODES];
__device__ float2 g_B[MAX_NODES];

// 1 if edge_index buffer holds int64 elements, 0 if int32.
__device__ int g_idx_is64;

// ---------------------------------------------------------------------------
// Kernel 1: warp-per-node partial logit computation.
// Each lane issues ONE float4 load (LDG.128): lane k owns columns 4k..4k+3.
// One warp streams a node's 128 floats as 4 coalesced 128B sectors and
// computes the 4 dot products against W staged in shared memory.
// Block 0 / thread 0 additionally performs the index-dtype detection
// (hidden under the HBM streaming of the other blocks).
// ---------------------------------------------------------------------------
__global__ __launch_bounds__(256)
void node_scores_kernel(const float4* __restrict__ emb4,
                        const float* __restrict__ W,
                        const float* __restrict__ bias,
                        const unsigned int* __restrict__ idx_words,
                        int n_nodes)
{
    __shared__ float Ws[512];  // W is [2, 256] row-major = 512 floats
    for (int i = threadIdx.x; i < 512; i += blockDim.x) Ws[i] = W[i];
    __syncthreads();

    // Index-dtype detection: for little-endian int64 node ids < 100000 every
    // odd 32-bit word is zero; for int32 data those words are random node ids
    // (P(all 32 == 0) ~ 1e-160). One thread, 32 independent loads.
    if (blockIdx.x == 0 && threadIdx.x == 0) {
        unsigned int acc = 0;
#pragma unroll
        for (int i = 1; i < 64; i += 2) acc |= idx_words[i];
        g_idx_is64 = (acc == 0u) ? 1 : 0;
    }

    const int warp = (int)((blockIdx.x * (unsigned)blockDim.x + threadIdx.x) >> 5);
    const int lane = threadIdx.x & 31;
    if (warp >= n_nodes) return;

    // Lane k loads emb[node][4k..4k+3] as one float4.
    const float4 v = __ldg(&emb4[(size_t)warp * 32 + lane]);
    const int k = lane * 4;

    float a0, b0, a1, b1;
    a0 = v.x * Ws[k];         a0 = fmaf(v.y, Ws[k+1],       a0);
    a0 = fmaf(v.z, Ws[k+2],       a0); a0 = fmaf(v.w, Ws[k+3],       a0);
    b0 = v.x * Ws[128+k];     b0 = fmaf(v.y, Ws[128+k+1],   b0);
    b0 = fmaf(v.z, Ws[128+k+2],   b0); b0 = fmaf(v.w, Ws[128+k+3],   b0);
    a1 = v.x * Ws[256+k];     a1 = fmaf(v.y, Ws[256+k+1],   a1);
    a1 = fmaf(v.z, Ws[256+k+2],   a1); a1 = fmaf(v.w, Ws[256+k+3],   a1);
    b1 = v.x * Ws[384+k];     b1 = fmaf(v.y, Ws[384+k+1],   b1);
    b1 = fmaf(v.z, Ws[384+k+2],   b1); b1 = fmaf(v.w, Ws[384+k+3],   b1);

#pragma unroll
    for (int off = 16; off; off >>= 1) {
        a0 += __shfl_xor_sync(0xFFFFFFFFu, a0, off);
        b0 += __shfl_xor_sync(0xFFFFFFFFu, b0, off);
        a1 += __shfl_xor_sync(0xFFFFFFFFu, a1, off);
        b1 += __shfl_xor_sync(0xFFFFFFFFu, b1, off);
    }

    if (lane == 0) {
        g_A[warp] = make_float2(a0 + bias[0], a1 + bias[1]);
        g_B[warp] = make_float2(b0, b1);
    }
}

// ---------------------------------------------------------------------------
// Kernel 2: per-edge gather from the L2-resident tables + 2-way softmax.
// 4 edges per thread: vector index loads (16B), 8 outstanding table gathers
// (MLP hides L2 latency), two float4 output stores.
// ---------------------------------------------------------------------------
__device__ __forceinline__ float2 softmax2(float2 A, float2 B)
{
    const float s0 = A.x + B.x;
    const float s1 = A.y + B.y;
    const float m   = fmaxf(s0, s1);
    const float e0  = __expf(s0 - m);
    const float e1  = __expf(s1 - m);
    const float inv = 1.0f / (e0 + e1);
    return make_float2(e0 * inv, e1 * inv);
}

__device__ __forceinline__ int clampN(int v)
{
    return min(max(v, 0), MAX_NODES - 1);
}

__global__ __launch_bounds__(256)
void edge_softmax_kernel(const void* __restrict__ ei_raw,
                         float4* __restrict__ out,   // [E/2] float4 = [E,2] f32
                         int n_edges)
{
    const int t  = (int)(blockIdx.x * (unsigned)blockDim.x + threadIdx.x);
    const int e0 = t * 4;
    if (e0 >= n_edges) return;

    int r[4], c[4];

    if (e0 + 4 <= n_edges) {
        if (g_idx_is64) {
            const longlong2* eiR = (const longlong2*)((const char*)ei_raw) + (e0 >> 1);
            const longlong2* eiC = (const longlong2*)((const char*)ei_raw + (size_t)n_edges * 8) + (e0 >> 1);
            const longlong2 r01 = eiR[0], r23 = eiR[1];
            const longlong2 c01 = eiC[0], c23 = eiC[1];
            r[0] = (int)r01.x; r[1] = (int)r01.y; r[2] = (int)r23.x; r[3] = (int)r23.y;
            c[0] = (int)c01.x; c[1] = (int)c01.y; c[2] = (int)c23.x; c[3] = (int)c23.y;
        } else {
            const int4 r4 = *(const int4*)((const int*)ei_raw + e0);
            const int4 c4 = *(const int4*)((const int*)ei_raw + n_edges + e0);
            r[0] = r4.x; r[1] = r4.y; r[2] = r4.z; r[3] = r4.w;
            c[0] = c4.x; c[1] = c4.y; c[2] = c4.z; c[3] = c4.w;
        }

        float2 A[4], B[4];
#pragma unroll
        for (int i = 0; i < 4; i++) {
            A[i] = g_A[clampN(r[i])];
            B[i] = g_B[clampN(c[i])];
        }

        float2 p0 = softmax2(A[0], B[0]);
        float2 p1 = softmax2(A[1], B[1]);
        float2 p2 = softmax2(A[2], B[2]);
        float2 p3 = softmax2(A[3], B[3]);

        out[t * 2 + 0] = make_float4(p0.x, p0.y, p1.x, p1.y);
        out[t * 2 + 1] = make_float4(p2.x, p2.y, p3.x, p3.y);
    } else {
        // Tail: scalar path
        float2* out2 = (float2*)out;
        for (int e = e0; e < n_edges; e++) {
            int rr, cc;
            if (g_idx_is64) {
                const long long* ei = (const long long*)ei_raw;
                rr = (int)ei[e];
                cc = (int)ei[n_edges + e];
            } else {
                const int* ei = (const int*)ei_raw;
                rr = ei[e];
                cc = ei[n_edges + e];
            }
            out2[e] = softmax2(g_A[clampN(rr)], g_B[clampN(cc)]);
        }
    }
}

// ---------------------------------------------------------------------------
extern "C" void kernel_launch(void* const* d_in, const int* in_sizes, int n_in,
                              void* d_out, int out_size)
{
    // Bind inputs by element count (all four are distinct):
    //   node_embeddings: N*128 (largest), edge_index: 2*E, W: 512, b: 2
    const float* emb  = nullptr; int emb_elems = 0;
    const void*  ei   = nullptr; int ei_elems  = 0;
    const float* W    = nullptr;
    const float* bias = nullptr;

    int i_emb = -1, i_ei = -1;
    for (int i = 0; i < n_in; i++) {
        if (i_emb < 0 || in_sizes[i] > in_sizes[i_emb]) i_emb = i;
    }
    for (int i = 0; i < n_in; i++) {
        if (i == i_emb) continue;
        if (i_ei < 0 || in_sizes[i] > in_sizes[i_ei]) i_ei = i;
    }
    emb = (const float*)d_in[i_emb]; emb_elems = in_sizes[i_emb];
    ei  = d_in[i_ei];                ei_elems  = in_sizes[i_ei];
    for (int i = 0; i < n_in; i++) {
        if (i == i_emb || i == i_ei) continue;
        if (in_sizes[i] > 16) W = (const float*)d_in[i];    // 512 elems
        else                  bias = (const float*)d_in[i]; // 2 elems
    }
    if (!W    && n_in > 2) W    = (const float*)d_in[2];
    if (!bias && n_in > 3) bias = (const float*)d_in[3];

    const int n_nodes = emb_elems / D_FEAT;
    const int n_edges = ei_elems / 2;

    // Kernel 1: one warp per node, 8 warps per block (+ inline dtype detect)
    {
        const int warps_per_block = 8;
        const int blocks = (n_nodes + warps_per_block - 1) / warps_per_block;
        node_scores_kernel<<<blocks, warps_per_block * 32>>>(
            (const float4*)emb, W, bias, (const unsigned int*)ei, n_nodes);
    }

    // Kernel 2: 4 edges per thread
    {
        const int threads = 256;
        const int edges_per_block = threads * 4;
        const int blocks = (n_edges + edges_per_block - 1) / edges_per_block;
        edge_softmax_kernel<<<blocks, threads>>>(ei, (float4*)d_out, n_edges);
    }
}

// round 6
// speedup vs baseline: 1.4021x; 1.4021x over previous
#include <cuda_runtime.h>
#include <cuda_bf16.h>
#include <cstdint>

// Problem constants (fixed by the dataset)
#define MAX_NODES 100000
#define D_FEAT    128
#define NPW       4      // nodes per warp in kernel 1
#define EPT       8      // edges per thread in kernel 2

// Per-node logit *difference* tables (sigmoid reformulation):
//   dA[n] = emb[n] . (W0-W1)[0:128]   + (b0-b1)   -- source side
//   dB[n] = emb[n] . (W0-W1)[128:256]              -- dest side
// Edge e=(r,c):  d = dA[r]+dB[c],  p0 = 1/(1+exp(-d)),  p1 = 1-p0.
__device__ float g_dA[MAX_NODES];
__device__ float g_dB[MAX_NODES];

// 1 if edge_index buffer holds int64 elements, 0 if int32.
__device__ int g_idx_is64;

// ---------------------------------------------------------------------------
// Kernel 1: warp computes NPW nodes. Lane k owns columns 4k..4k+3 (one
// LDG.128 per node -> MLP=NPW independent 16B loads per thread).
// Wd = W[0,:] - W[1,:] staged in smem, read as float4 (conflict-free LDS.128).
// Reduction: 6 shuffles per node (pair-sum, select, 4-level butterfly).
// Block 0 / thread 0 also performs the index-dtype detection.
// ---------------------------------------------------------------------------
__global__ __launch_bounds__(256)
void node_scores_kernel(const float4* __restrict__ emb4,
                        const float* __restrict__ W,
                        const float* __restrict__ bias,
                        const unsigned int* __restrict__ idx_words,
                        int n_nodes)
{
    __shared__ __align__(16) float Wd[256];   // W0 - W1, 256 floats
    for (int i = threadIdx.x; i < 256; i += blockDim.x)
        Wd[i] = W[i] - W[256 + i];
    __syncthreads();

    // Index-dtype detection: for little-endian int64 node ids < 100000 every
    // odd 32-bit word is zero; int32 data has random ids there
    // (P(all 32 == 0) ~ 1e-160).
    if (blockIdx.x == 0 && threadIdx.x == 0) {
        unsigned int acc = 0;
#pragma unroll
        for (int i = 1; i < 64; i += 2) acc |= idx_words[i];
        g_idx_is64 = (acc == 0u) ? 1 : 0;
    }

    const int warp = (int)((blockIdx.x * (unsigned)blockDim.x + threadIdx.x) >> 5);
    const int lane = threadIdx.x & 31;
    const int node0 = warp * NPW;
    if (node0 >= n_nodes) return;

    const float dbias = bias[0] - bias[1];

    const float4* wd4 = (const float4*)Wd;
    const float4 wsrc = wd4[lane];        // (W0-W1)[4k..4k+3]
    const float4 wdst = wd4[32 + lane];   // (W0-W1)[128+4k..128+4k+3]

    // Batch the independent embedding loads first (MLP = NPW).
    float4 v[NPW];
#pragma unroll
    for (int i = 0; i < NPW; i++) {
        const int n = node0 + i;
        v[i] = (n < n_nodes) ? __ldg(&emb4[(size_t)n * 32 + lane])
                             : make_float4(0.f, 0.f, 0.f, 0.f);
    }

#pragma unroll
    for (int i = 0; i < NPW; i++) {
        float da = v[i].x * wsrc.x;
        da = fmaf(v[i].y, wsrc.y, da);
        da = fmaf(v[i].z, wsrc.z, da);
        da = fmaf(v[i].w, wsrc.w, da);
        float db = v[i].x * wdst.x;
        db = fmaf(v[i].y, wdst.y, db);
        db = fmaf(v[i].z, wdst.z, db);
        db = fmaf(v[i].w, wdst.w, db);

        // 6-shuffle dual reduction:
        da += __shfl_xor_sync(0xFFFFFFFFu, da, 1);
        db += __shfl_xor_sync(0xFFFFFFFFu, db, 1);
        float sel = (lane & 1) ? db : da;
        sel += __shfl_xor_sync(0xFFFFFFFFu, sel, 2);
        sel += __shfl_xor_sync(0xFFFFFFFFu, sel, 4);
        sel += __shfl_xor_sync(0xFFFFFFFFu, sel, 8);
        sel += __shfl_xor_sync(0xFFFFFFFFu, sel, 16);
        // Now every even lane holds full da, every odd lane full db.

        const int n = node0 + i;
        if ((lane >> 1) == i && n < n_nodes) {
            if (lane & 1) g_dB[n] = sel;
            else          g_dA[n] = sel + dbias;
        }
    }
}

// ---------------------------------------------------------------------------
// Kernel 2: EPT edges per thread. Vector index loads, 2*EPT outstanding
// 4B random gathers from the L2-resident 800KB tables, sigmoid, float4 stores.
// ---------------------------------------------------------------------------
__device__ __forceinline__ int clampN(int v)
{
    return min(max(v, 0), MAX_NODES - 1);
}

__device__ __forceinline__ float2 edge_prob(float d)
{
    const float t   = __expf(-d);
    const float inv = 1.0f / (1.0f + t);
    return make_float2(inv, t * inv);   // (p0, p1), p0+p1 = 1 exactly-ish
}

__global__ __launch_bounds__(256)
void edge_softmax_kernel(const void* __restrict__ ei_raw,
                         float4* __restrict__ out4,  // [E/2] float4 = [E,2] f32
                         int n_edges)
{
    const int t  = (int)(blockIdx.x * (unsigned)blockDim.x + threadIdx.x);
    const int e0 = t * EPT;
    if (e0 >= n_edges) return;

    if (e0 + EPT <= n_edges) {
        int r[EPT], c[EPT];
        if (g_idx_is64) {
            const longlong2* eiR = (const longlong2*)ei_raw + (e0 >> 1);
            const longlong2* eiC = (const longlong2*)((const char*)ei_raw + (size_t)n_edges * 8) + (e0 >> 1);
#pragma unroll
            for (int j = 0; j < EPT / 2; j++) {
                const longlong2 rv = eiR[j];
                const longlong2 cv = eiC[j];
                r[2*j] = (int)rv.x; r[2*j+1] = (int)rv.y;
                c[2*j] = (int)cv.x; c[2*j+1] = (int)cv.y;
            }
        } else {
            const int4* eiR = (const int4*)((const int*)ei_raw + e0);
            const int4* eiC = (const int4*)((const int*)ei_raw + n_edges + e0);
#pragma unroll
            for (int j = 0; j < EPT / 4; j++) {
                const int4 rv = eiR[j];
                const int4 cv = eiC[j];
                r[4*j] = rv.x; r[4*j+1] = rv.y; r[4*j+2] = rv.z; r[4*j+3] = rv.w;
                c[4*j] = cv.x; c[4*j+1] = cv.y; c[4*j+2] = cv.z; c[4*j+3] = cv.w;
            }
        }

        // Issue all 2*EPT independent gathers before consuming any (max MLP).
        float dA[EPT], dB[EPT];
#pragma unroll
        for (int i = 0; i < EPT; i++) dA[i] = __ldg(&g_dA[clampN(r[i])]);
#pragma unroll
        for (int i = 0; i < EPT; i++) dB[i] = __ldg(&g_dB[clampN(c[i])]);

#pragma unroll
        for (int j = 0; j < EPT / 2; j++) {
            const float2 p0 = edge_prob(dA[2*j]   + dB[2*j]);
            const float2 p1 = edge_prob(dA[2*j+1] + dB[2*j+1]);
            out4[(size_t)t * (EPT / 2) + j] = make_float4(p0.x, p0.y, p1.x, p1.y);
        }
    } else {
        // Tail: scalar path
        float2* out2 = (float2*)out4;
        for (int e = e0; e < n_edges; e++) {
            int rr, cc;
            if (g_idx_is64) {
                const long long* ei = (const long long*)ei_raw;
                rr = (int)ei[e];
                cc = (int)ei[n_edges + e];
            } else {
                const int* ei = (const int*)ei_raw;
                rr = ei[e];
                cc = ei[n_edges + e];
            }
            out2[e] = edge_prob(g_dA[clampN(rr)] + g_dB[clampN(cc)]);
        }
    }
}

// ---------------------------------------------------------------------------
extern "C" void kernel_launch(void* const* d_in, const int* in_sizes, int n_in,
                              void* d_out, int out_size)
{
    // Bind inputs by element count (all four are distinct):
    //   node_embeddings: N*128 (largest), edge_index: 2*E, W: 512, b: 2
    const float* emb  = nullptr; int emb_elems = 0;
    const void*  ei   = nullptr; int ei_elems  = 0;
    const float* W    = nullptr;
    const float* bias = nullptr;

    int i_emb = -1, i_ei = -1;
    for (int i = 0; i < n_in; i++) {
        if (i_emb < 0 || in_sizes[i] > in_sizes[i_emb]) i_emb = i;
    }
    for (int i = 0; i < n_in; i++) {
        if (i == i_emb) continue;
        if (i_ei < 0 || in_sizes[i] > in_sizes[i_ei]) i_ei = i;
    }
    emb = (const float*)d_in[i_emb]; emb_elems = in_sizes[i_emb];
    ei  = d_in[i_ei];                ei_elems  = in_sizes[i_ei];
    for (int i = 0; i < n_in; i++) {
        if (i == i_emb || i == i_ei) continue;
        if (in_sizes[i] > 16) W = (const float*)d_in[i];    // 512 elems
        else                  bias = (const float*)d_in[i]; // 2 elems
    }
    if (!W    && n_in > 2) W    = (const float*)d_in[2];
    if (!bias && n_in > 3) bias = (const float*)d_in[3];

    const int n_nodes = emb_elems / D_FEAT;
    const int n_edges = ei_elems / 2;

    // Kernel 1: NPW nodes per warp, 8 warps per block (+ inline dtype detect)
    {
        const int nodes_per_block = 8 * NPW;
        const int blocks = (n_nodes + nodes_per_block - 1) / nodes_per_block;
        node_scores_kernel<<<blocks, 256>>>(
            (const float4*)emb, W, bias, (const unsigned int*)ei, n_nodes);
    }

    // Kernel 2: EPT edges per thread
    {
        const int threads = 256;
        const int edges_per_block = threads * EPT;
        const int blocks = (n_edges + edges_per_block - 1) / edges_per_block;
        edge_softmax_kernel<<<blocks, threads>>>(ei, (float4*)d_out, n_edges);
    }
}